// round 1
// baseline (speedup 1.0000x reference)
#include <cuda_runtime.h>
#include <math.h>

#define NMAX   50000
#define EMAXT  460000   // edges + self loops upper bound
#define HEADS  4
#define HID    64
#define GRAPHS 64
#define NEG    0.2f
#define BN_EPS 1e-5f

// ---------------- scratch (device globals; no allocations allowed) ----------
__device__ float g_xh [NMAX * 256];      // per-layer projected features [N,H*C]
__device__ float g_agg[NMAX * 256];      // layer0 aggregated (concat) output
__device__ float g_as [NMAX * 4];
__device__ float g_ad [NMAX * 4];
__device__ float g_rep[3 * NMAX * 64];   // reps for jumping knowledge
__device__ float g_cat[NMAX * 192];
__device__ float g_tmp[NMAX * 64];
__device__ float g_hj [NMAX * 64];       // jump output
__device__ int   g_deg[NMAX + 1];
__device__ int   g_off[NMAX + 1];
__device__ int   g_cur[NMAX];
__device__ int   g_csr[EMAXT];
__device__ unsigned g_maxenc[GRAPHS];
__device__ float g_sumexp[GRAPHS];
__device__ float g_hg[GRAPHS * 64];
__device__ float g_logit[NMAX];

// ---------------- helpers ----------------
__device__ __forceinline__ unsigned fenc(float f) {
    unsigned u = __float_as_uint(f);
    return (u & 0x80000000u) ? ~u : (u | 0x80000000u);
}
__device__ __forceinline__ float fdec(unsigned u) {
    return (u & 0x80000000u) ? __uint_as_float(u & 0x7fffffffu)
                             : __uint_as_float(~u);
}

// ---------------- init ----------------
__global__ void init_kernel(int n) {
    int i = blockIdx.x * blockDim.x + threadIdx.x;
    if (i < n) g_deg[i] = 1;                 // self loop
    if (i < GRAPHS) { g_maxenc[i] = 0u; g_sumexp[i] = 0.f; }
    if (i < GRAPHS * 64) g_hg[i] = 0.f;
}

__global__ void count_kernel(const int* __restrict__ ei, int e) {
    int i = blockIdx.x * blockDim.x + threadIdx.x;
    if (i < e) atomicAdd(&g_deg[ei[e + i]], 1);   // dst row is second
}

// one-block inclusive/exclusive scan over n entries
__global__ void scan_kernel(int n) {
    __shared__ int sh[1024];
    __shared__ int carry;
    int tid = threadIdx.x;
    if (tid == 0) carry = 0;
    __syncthreads();
    for (int base = 0; base < n; base += 1024) {
        int i = base + tid;
        int v = (i < n) ? g_deg[i] : 0;
        sh[tid] = v;
        __syncthreads();
        for (int s = 1; s < 1024; s <<= 1) {
            int t = (tid >= s) ? sh[tid - s] : 0;
            __syncthreads();
            sh[tid] += t;
            __syncthreads();
        }
        int incl = sh[tid];
        if (i < n) g_off[i] = carry + incl - v;
        __syncthreads();
        if (tid == 1023) carry += sh[1023];
        __syncthreads();
    }
    if (tid == 0) g_off[n] = carry;
}

__global__ void cursor_kernel(int n) {
    int i = blockIdx.x * blockDim.x + threadIdx.x;
    if (i < n) g_cur[i] = g_off[i];
}
__global__ void fill_edges_kernel(const int* __restrict__ ei, int e) {
    int i = blockIdx.x * blockDim.x + threadIdx.x;
    if (i < e) {
        int dst = ei[e + i];
        int pos = atomicAdd(&g_cur[dst], 1);
        g_csr[pos] = ei[i];                  // src
    }
}
__global__ void fill_loops_kernel(int n) {
    int i = blockIdx.x * blockDim.x + threadIdx.x;
    if (i < n) {
        int pos = atomicAdd(&g_cur[i], 1);
        g_csr[pos] = i;
    }
}

// ---------------- generic tiled fp32 GEMM: C[M,NC] = A[M,K]@B[K,NC] (+bias) --
__global__ void gemm_kernel(const float* __restrict__ A, const float* __restrict__ B,
                            const float* __restrict__ bias, float* __restrict__ C,
                            int M, int K, int NC) {
    __shared__ float As[64][17];
    __shared__ float Bs[16][65];
    int tx = threadIdx.x, ty = threadIdx.y;
    int tid = ty * 16 + tx;
    int row0 = blockIdx.y * 64, col0 = blockIdx.x * 64;
    float acc[4][4] = {};
    for (int k0 = 0; k0 < K; k0 += 16) {
#pragma unroll
        for (int i = 0; i < 4; i++) {
            int idx = tid + i * 256;
            int m = idx >> 4, kk = idx & 15;
            int gm = row0 + m, gk = k0 + kk;
            As[m][kk] = (gm < M && gk < K) ? A[(size_t)gm * K + gk] : 0.f;
        }
#pragma unroll
        for (int i = 0; i < 4; i++) {
            int idx = tid + i * 256;
            int kk = idx >> 6, nn = idx & 63;
            int gk = k0 + kk, gn = col0 + nn;
            Bs[kk][nn] = (gk < K && gn < NC) ? B[(size_t)gk * NC + gn] : 0.f;
        }
        __syncthreads();
#pragma unroll
        for (int kk = 0; kk < 16; kk++) {
            float a[4], b[4];
#pragma unroll
            for (int i = 0; i < 4; i++) a[i] = As[ty * 4 + i][kk];
#pragma unroll
            for (int j = 0; j < 4; j++) b[j] = Bs[kk][tx * 4 + j];
#pragma unroll
            for (int i = 0; i < 4; i++)
#pragma unroll
                for (int j = 0; j < 4; j++) acc[i][j] += a[i] * b[j];
        }
        __syncthreads();
    }
#pragma unroll
    for (int i = 0; i < 4; i++) {
        int gm = row0 + ty * 4 + i;
        if (gm >= M) continue;
#pragma unroll
        for (int j = 0; j < 4; j++) {
            int gn = col0 + tx * 4 + j;
            if (gn < NC)
                C[(size_t)gm * NC + gn] = acc[i][j] + (bias ? bias[gn] : 0.f);
        }
    }
}

// ---------------- per-node attention coefficients ----------------
__global__ void attn_kernel(const float* __restrict__ a_src,
                            const float* __restrict__ a_dst, int n) {
    __shared__ float s_src[256], s_dst[256];
    int tid = threadIdx.x;
    for (int i = tid; i < 256; i += blockDim.x) { s_src[i] = a_src[i]; s_dst[i] = a_dst[i]; }
    __syncthreads();
    int w = blockIdx.x * (blockDim.x >> 5) + (tid >> 5);
    int lane = tid & 31;
    if (w >= n) return;
    const float* xr = g_xh + (size_t)w * 256;
    float ps[4], pd[4];
#pragma unroll
    for (int h = 0; h < 4; h++) {
        int f0 = h * 64 + lane, f1 = f0 + 32;
        float x0 = xr[f0], x1 = xr[f1];
        ps[h] = x0 * s_src[f0] + x1 * s_src[f1];
        pd[h] = x0 * s_dst[f0] + x1 * s_dst[f1];
    }
#pragma unroll
    for (int h = 0; h < 4; h++)
#pragma unroll
        for (int o = 16; o > 0; o >>= 1) {
            ps[h] += __shfl_xor_sync(0xffffffffu, ps[h], o);
            pd[h] += __shfl_xor_sync(0xffffffffu, pd[h], o);
        }
    if (lane == 0) {
#pragma unroll
        for (int h = 0; h < 4; h++) { g_as[w * 4 + h] = ps[h]; g_ad[w * 4 + h] = pd[h]; }
    }
}

// online-softmax GAT aggregation, one warp per dst node, concat output (+bias)
__global__ void agg_concat_kernel(const float* __restrict__ bias, int n) {
    int w = blockIdx.x * (blockDim.x >> 5) + (threadIdx.x >> 5);
    int lane = threadIdx.x & 31;
    if (w >= n) return;
    float m0 = -1e30f, m1 = -1e30f, m2 = -1e30f, m3 = -1e30f;
    float s0 = 0, s1 = 0, s2 = 0, s3 = 0;
    float acc[8] = {};
    float adh = (lane < 4) ? g_ad[w * 4 + lane] : 0.f;
    int e0 = g_off[w], e1 = g_off[w + 1];
    for (int e = e0; e < e1; e++) {
        int src = g_csr[e];
        float l = 0.f;
        if (lane < 4) {
            float t = g_as[src * 4 + lane] + adh;
            l = t > 0.f ? t : NEG * t;
        }
        float l0 = __shfl_sync(0xffffffffu, l, 0);
        float l1 = __shfl_sync(0xffffffffu, l, 1);
        float l2 = __shfl_sync(0xffffffffu, l, 2);
        float l3 = __shfl_sync(0xffffffffu, l, 3);
        float nm0 = fmaxf(m0, l0), nm1 = fmaxf(m1, l1), nm2 = fmaxf(m2, l2), nm3 = fmaxf(m3, l3);
        float sc0 = __expf(m0 - nm0), sc1 = __expf(m1 - nm1), sc2 = __expf(m2 - nm2), sc3 = __expf(m3 - nm3);
        float w0 = __expf(l0 - nm0), w1 = __expf(l1 - nm1), w2 = __expf(l2 - nm2), w3 = __expf(l3 - nm3);
        s0 = s0 * sc0 + w0; s1 = s1 * sc1 + w1; s2 = s2 * sc2 + w2; s3 = s3 * sc3 + w3;
        m0 = nm0; m1 = nm1; m2 = nm2; m3 = nm3;
        const float* xr = g_xh + (size_t)src * 256;
        acc[0] = acc[0] * sc0 + w0 * xr[lane];
        acc[1] = acc[1] * sc0 + w0 * xr[lane + 32];
        acc[2] = acc[2] * sc1 + w1 * xr[lane + 64];
        acc[3] = acc[3] * sc1 + w1 * xr[lane + 96];
        acc[4] = acc[4] * sc2 + w2 * xr[lane + 128];
        acc[5] = acc[5] * sc2 + w2 * xr[lane + 160];
        acc[6] = acc[6] * sc3 + w3 * xr[lane + 192];
        acc[7] = acc[7] * sc3 + w3 * xr[lane + 224];
    }
    size_t o = (size_t)w * 256;
    g_agg[o + lane]       = acc[0] / s0 + bias[lane];
    g_agg[o + lane + 32]  = acc[1] / s0 + bias[lane + 32];
    g_agg[o + lane + 64]  = acc[2] / s1 + bias[lane + 64];
    g_agg[o + lane + 96]  = acc[3] / s1 + bias[lane + 96];
    g_agg[o + lane + 128] = acc[4] / s2 + bias[lane + 128];
    g_agg[o + lane + 160] = acc[5] / s2 + bias[lane + 160];
    g_agg[o + lane + 192] = acc[6] / s3 + bias[lane + 192];
    g_agg[o + lane + 224] = acc[7] / s3 + bias[lane + 224];
}

// aggregation for layers 1/2: mean over heads + bias + BN + ELU + residual
__global__ void agg_mean_kernel(const float* __restrict__ bias,
                                const float* __restrict__ gamma, const float* __restrict__ beta,
                                const float* __restrict__ mean,  const float* __restrict__ var,
                                const float* __restrict__ h_in, float* __restrict__ h_out, int n) {
    int w = blockIdx.x * (blockDim.x >> 5) + (threadIdx.x >> 5);
    int lane = threadIdx.x & 31;
    if (w >= n) return;
    float m0 = -1e30f, m1 = -1e30f, m2 = -1e30f, m3 = -1e30f;
    float s0 = 0, s1 = 0, s2 = 0, s3 = 0;
    float acc[8] = {};
    float adh = (lane < 4) ? g_ad[w * 4 + lane] : 0.f;
    int e0 = g_off[w], e1 = g_off[w + 1];
    for (int e = e0; e < e1; e++) {
        int src = g_csr[e];
        float l = 0.f;
        if (lane < 4) {
            float t = g_as[src * 4 + lane] + adh;
            l = t > 0.f ? t : NEG * t;
        }
        float l0 = __shfl_sync(0xffffffffu, l, 0);
        float l1 = __shfl_sync(0xffffffffu, l, 1);
        float l2 = __shfl_sync(0xffffffffu, l, 2);
        float l3 = __shfl_sync(0xffffffffu, l, 3);
        float nm0 = fmaxf(m0, l0), nm1 = fmaxf(m1, l1), nm2 = fmaxf(m2, l2), nm3 = fmaxf(m3, l3);
        float sc0 = __expf(m0 - nm0), sc1 = __expf(m1 - nm1), sc2 = __expf(m2 - nm2), sc3 = __expf(m3 - nm3);
        float w0 = __expf(l0 - nm0), w1 = __expf(l1 - nm1), w2 = __expf(l2 - nm2), w3 = __expf(l3 - nm3);
        s0 = s0 * sc0 + w0; s1 = s1 * sc1 + w1; s2 = s2 * sc2 + w2; s3 = s3 * sc3 + w3;
        m0 = nm0; m1 = nm1; m2 = nm2; m3 = nm3;
        const float* xr = g_xh + (size_t)src * 256;
        acc[0] = acc[0] * sc0 + w0 * xr[lane];
        acc[1] = acc[1] * sc0 + w0 * xr[lane + 32];
        acc[2] = acc[2] * sc1 + w1 * xr[lane + 64];
        acc[3] = acc[3] * sc1 + w1 * xr[lane + 96];
        acc[4] = acc[4] * sc2 + w2 * xr[lane + 128];
        acc[5] = acc[5] * sc2 + w2 * xr[lane + 160];
        acc[6] = acc[6] * sc3 + w3 * xr[lane + 192];
        acc[7] = acc[7] * sc3 + w3 * xr[lane + 224];
    }
    float i0 = 1.f / s0, i1 = 1.f / s1, i2 = 1.f / s2, i3 = 1.f / s3;
    // channel = lane (even accs), channel = lane+32 (odd accs)
    float v0 = 0.25f * (acc[0] * i0 + acc[2] * i1 + acc[4] * i2 + acc[6] * i3) + bias[lane];
    float v1 = 0.25f * (acc[1] * i0 + acc[3] * i1 + acc[5] * i2 + acc[7] * i3) + bias[lane + 32];
    int c0 = lane, c1 = lane + 32;
    v0 = (v0 - mean[c0]) * rsqrtf(var[c0] + BN_EPS) * gamma[c0] + beta[c0];
    v1 = (v1 - mean[c1]) * rsqrtf(var[c1] + BN_EPS) * gamma[c1] + beta[c1];
    v0 = v0 > 0.f ? v0 : expm1f(v0);
    v1 = v1 > 0.f ? v1 : expm1f(v1);
    size_t o = (size_t)w * 64;
    h_out[o + c0] = v0 + h_in[o + c0];
    h_out[o + c1] = v1 + h_in[o + c1];
}

// BN + ELU elementwise (layer0, no residual)
__global__ void bn_elu_kernel(const float* __restrict__ in,
                              const float* __restrict__ gamma, const float* __restrict__ beta,
                              const float* __restrict__ mean,  const float* __restrict__ var,
                              float* __restrict__ out, int total) {
    int i = blockIdx.x * blockDim.x + threadIdx.x;
    if (i >= total) return;
    int c = i & 63;
    float v = (in[i] - mean[c]) * rsqrtf(var[c] + BN_EPS) * gamma[c] + beta[c];
    out[i] = v > 0.f ? v : expm1f(v);
}

__global__ void concat_kernel(int n) {
    int i = blockIdx.x * blockDim.x + threadIdx.x;
    if (i >= n * 192) return;
    int node = i / 192, j = i % 192;
    int layer = j >> 6, c = j & 63;
    g_cat[i] = g_rep[(size_t)layer * NMAX * 64 + (size_t)node * 64 + c];
}

// pooling pass 1: logits + per-graph max
__global__ void pool1_kernel(const float* __restrict__ attW, const float* __restrict__ attB,
                             const int* __restrict__ batch, int n) {
    int w = blockIdx.x * (blockDim.x >> 5) + (threadIdx.x >> 5);
    int lane = threadIdx.x & 31;
    if (w >= n) return;
    const float* hr = g_hj + (size_t)w * 64;
    float p = hr[lane] * attW[lane] + hr[lane + 32] * attW[lane + 32];
#pragma unroll
    for (int o = 16; o > 0; o >>= 1) p += __shfl_xor_sync(0xffffffffu, p, o);
    if (lane == 0) {
        float v = p + attB[0];
        g_logit[w] = v;
        atomicMax(&g_maxenc[batch[w]], fenc(v));
    }
}

// pooling pass 2: unnormalized weighted sum + denom
__global__ void pool2_kernel(const int* __restrict__ batch, int n) {
    int w = blockIdx.x * (blockDim.x >> 5) + (threadIdx.x >> 5);
    int lane = threadIdx.x & 31;
    if (w >= n) return;
    int b = batch[w];
    float ev = __expf(g_logit[w] - fdec(g_maxenc[b]));
    if (lane == 0) atomicAdd(&g_sumexp[b], ev);
    const float* hr = g_hj + (size_t)w * 64;
    atomicAdd(&g_hg[b * 64 + lane], ev * hr[lane]);
    atomicAdd(&g_hg[b * 64 + lane + 32], ev * hr[lane + 32]);
}

__global__ void classifier_kernel(const float* __restrict__ W1, const float* __restrict__ b1,
                                  const float* __restrict__ W2, const float* __restrict__ b2,
                                  float* __restrict__ out) {
    int g = threadIdx.x;
    if (g >= GRAPHS) return;
    float s = g_sumexp[g];
    float inv = (s > 0.f) ? 1.f / s : 0.f;
    float hid[32];
#pragma unroll
    for (int j = 0; j < 32; j++) {
        float a = b1[j];
        for (int c = 0; c < 64; c++) a += g_hg[g * 64 + c] * inv * W1[c * 32 + j];
        hid[j] = a > 0.f ? a : 0.f;
    }
#pragma unroll
    for (int k = 0; k < 2; k++) {
        float o = b2[k];
#pragma unroll
        for (int j = 0; j < 32; j++) o += hid[j] * W2[j * 2 + k];
        out[g * 2 + k] = o;
    }
}

// ---------------- host ----------------
extern "C" void kernel_launch(void* const* d_in, const int* in_sizes, int n_in,
                              void* d_out, int out_size) {
    const float* x        = (const float*)d_in[0];
    const int*   ei       = (const int*)d_in[1];
    const int*   batch    = (const int*)d_in[2];
    const float* conv0_W  = (const float*)d_in[3];
    const float* c0_asrc  = (const float*)d_in[4];
    const float* c0_adst  = (const float*)d_in[5];
    const float* c0_bias  = (const float*)d_in[6];
    const float* pre0_W   = (const float*)d_in[7];
    const float* pre0_b   = (const float*)d_in[8];
    const float* convs_W  = (const float*)d_in[9];
    const float* cs_asrc  = (const float*)d_in[10];
    const float* cs_adst  = (const float*)d_in[11];
    const float* cs_bias  = (const float*)d_in[12];
    const float* bn_g     = (const float*)d_in[13];
    const float* bn_b     = (const float*)d_in[14];
    const float* bn_m     = (const float*)d_in[15];
    const float* bn_v     = (const float*)d_in[16];
    const float* jump_W   = (const float*)d_in[17];
    const float* jump_b   = (const float*)d_in[18];
    const float* att_W    = (const float*)d_in[19];
    const float* att_b    = (const float*)d_in[20];
    const float* cls_W1   = (const float*)d_in[21];
    const float* cls_b1   = (const float*)d_in[22];
    const float* cls_W2   = (const float*)d_in[23];
    const float* cls_b2   = (const float*)d_in[24];

    int n = in_sizes[0] / 128;
    int e = in_sizes[1] / 2;

    float *p_xh, *p_agg, *p_rep, *p_cat, *p_tmp, *p_hj;
    cudaGetSymbolAddress((void**)&p_xh,  g_xh);
    cudaGetSymbolAddress((void**)&p_agg, g_agg);
    cudaGetSymbolAddress((void**)&p_rep, g_rep);
    cudaGetSymbolAddress((void**)&p_cat, g_cat);
    cudaGetSymbolAddress((void**)&p_tmp, g_tmp);
    cudaGetSymbolAddress((void**)&p_hj,  g_hj);

    const int T = 256;
    int nb  = (n + T - 1) / T;
    int ebN = (e + T - 1) / T;
    int wb  = (n + 7) / 8;        // 8 warps per block kernels

    // CSR build
    init_kernel<<<nb, T>>>(n);
    count_kernel<<<ebN, T>>>(ei, e);
    scan_kernel<<<1, 1024>>>(n);
    cursor_kernel<<<nb, T>>>(n);
    fill_edges_kernel<<<ebN, T>>>(ei, e);
    fill_loops_kernel<<<nb, T>>>(n);

    dim3 tb(16, 16);
    int mgrid = (n + 63) / 64;

    // ---- layer 0 (concat) ----
    gemm_kernel<<<dim3(4, mgrid), tb>>>(x, conv0_W, nullptr, p_xh, n, 128, 256);
    attn_kernel<<<wb, T>>>(c0_asrc, c0_adst, n);
    agg_concat_kernel<<<wb, T>>>(c0_bias, n);
    gemm_kernel<<<dim3(1, mgrid), tb>>>(p_agg, pre0_W, pre0_b, p_tmp, n, 256, 64);
    bn_elu_kernel<<<(n * 64 + T - 1) / T, T>>>(p_tmp, bn_g, bn_b, bn_m, bn_v, p_rep, n * 64);

    // ---- layers 1,2 (mean heads, fused BN/ELU/residual) ----
    for (int i = 0; i < 2; i++) {
        const float* rin  = p_rep + (size_t)i * NMAX * 64;
        float*       rout = p_rep + (size_t)(i + 1) * NMAX * 64;
        gemm_kernel<<<dim3(4, mgrid), tb>>>(rin, convs_W + (size_t)i * 64 * 256, nullptr,
                                            p_xh, n, 64, 256);
        attn_kernel<<<wb, T>>>(cs_asrc + i * 256, cs_adst + i * 256, n);
        agg_mean_kernel<<<wb, T>>>(cs_bias + i * 64,
                                   bn_g + (i + 1) * 64, bn_b + (i + 1) * 64,
                                   bn_m + (i + 1) * 64, bn_v + (i + 1) * 64,
                                   rin, rout, n);
    }

    // ---- jumping knowledge + pooling + classifier ----
    concat_kernel<<<(n * 192 + T - 1) / T, T>>>(n);
    gemm_kernel<<<dim3(1, mgrid), tb>>>(p_cat, jump_W, jump_b, p_hj, n, 192, 64);
    pool1_kernel<<<wb, T>>>(att_W, att_b, batch, n);
    pool2_kernel<<<wb, T>>>(batch, n);
    classifier_kernel<<<1, 64>>>(cls_W1, cls_b1, cls_W2, cls_b2, (float*)d_out);
}

// round 2
// speedup vs baseline: 2.1888x; 2.1888x over previous
#include <cuda_runtime.h>
#include <math.h>

#define NMAX   50000
#define HEADS  4
#define HID    64
#define GRAPHS 64
#define NEG    0.2f
#define BN_EPS 1e-5f
#define EMAXT  460000

// ---------------- scratch (device globals; no allocations allowed) ----------
__device__ float g_xh [NMAX * 256];      // projected features [N,H*C]
__device__ float g_agg[NMAX * 256];      // layer0 aggregated (concat) output
__device__ float g_as [NMAX * 4];
__device__ float g_ad [NMAX * 4];
__device__ float g_rep[3 * NMAX * 64];   // reps for jumping knowledge
__device__ float g_hj [NMAX * 64];       // jump output
__device__ int   g_deg[NMAX + 1];
__device__ int   g_off[NMAX + 1];
__device__ int   g_cur[NMAX];
__device__ int   g_csr[EMAXT];
__device__ unsigned g_maxenc[GRAPHS];
__device__ float g_sumexp[GRAPHS];
__device__ float g_hg[GRAPHS * 64];
__device__ float g_logit[NMAX];

// ---------------- helpers ----------------
__device__ __forceinline__ unsigned fenc(float f) {
    unsigned u = __float_as_uint(f);
    return (u & 0x80000000u) ? ~u : (u | 0x80000000u);
}
__device__ __forceinline__ float fdec(unsigned u) {
    return (u & 0x80000000u) ? __uint_as_float(u & 0x7fffffffu)
                             : __uint_as_float(~u);
}
__device__ __forceinline__ float cvt_tf32(float x) {
    unsigned o;
    asm("cvt.rna.tf32.f32 %0, %1;" : "=r"(o) : "f"(x));
    return __uint_as_float(o);
}
__device__ __forceinline__ void mma_tf32(float c[4], const unsigned a[4], const unsigned b[2]) {
    asm volatile("mma.sync.aligned.m16n8k8.row.col.f32.tf32.tf32.f32 "
                 "{%0,%1,%2,%3},{%4,%5,%6,%7},{%8,%9},{%0,%1,%2,%3};"
                 : "+f"(c[0]), "+f"(c[1]), "+f"(c[2]), "+f"(c[3])
                 : "r"(a[0]), "r"(a[1]), "r"(a[2]), "r"(a[3]), "r"(b[0]), "r"(b[1]));
}

// ---------------- init ----------------
__global__ void init_kernel(int n) {
    int i = blockIdx.x * blockDim.x + threadIdx.x;
    if (i < n) g_deg[i] = 1;                 // self loop
    if (i < GRAPHS) { g_maxenc[i] = 0u; g_sumexp[i] = 0.f; }
    if (i < GRAPHS * 64) g_hg[i] = 0.f;
}

__global__ void count_kernel(const int* __restrict__ ei, int e) {
    int i = blockIdx.x * blockDim.x + threadIdx.x;
    if (i < e) atomicAdd(&g_deg[ei[e + i]], 1);   // dst row is second
}

// one-block warp-shuffle scan; also places self-loop in slot 0 and sets cursor
__global__ void scan_kernel(int n) {
    __shared__ int wsum[32];
    __shared__ int carry;
    int tid = threadIdx.x, lane = tid & 31, wid = tid >> 5;
    if (tid == 0) carry = 0;
    __syncthreads();
    for (int base = 0; base < n; base += 1024) {
        int i = base + tid;
        int v = (i < n) ? g_deg[i] : 0;
        int incl = v;
#pragma unroll
        for (int o = 1; o < 32; o <<= 1) {
            int t = __shfl_up_sync(0xffffffffu, incl, o);
            if (lane >= o) incl += t;
        }
        if (lane == 31) wsum[wid] = incl;
        __syncthreads();
        if (wid == 0) {
            int s = wsum[lane];
#pragma unroll
            for (int o = 1; o < 32; o <<= 1) {
                int t = __shfl_up_sync(0xffffffffu, s, o);
                if (lane >= o) s += t;
            }
            wsum[lane] = s;
        }
        __syncthreads();
        int wpre = wid ? wsum[wid - 1] : 0;
        int excl = carry + wpre + incl - v;
        if (i < n) {
            g_off[i] = excl;
            g_csr[excl] = i;       // self loop takes first slot
            g_cur[i] = excl + 1;
        }
        __syncthreads();
        if (tid == 0) carry += wsum[31];
        __syncthreads();
    }
    if (tid == 0) g_off[n] = carry;
}

__global__ void fill_edges_kernel(const int* __restrict__ ei, int e) {
    int i = blockIdx.x * blockDim.x + threadIdx.x;
    if (i < e) {
        int dst = ei[e + i];
        int pos = atomicAdd(&g_cur[dst], 1);
        g_csr[pos] = ei[i];                  // src
    }
}

// ---------- TF32 tensor-core GEMM: C[M,NC] = A[M,K] @ B[K,NC] ----------
// BM=128, BN=64, BK=32, 256 threads (8 warps: 4x2, warp tile 32x32)
// AMODE 0: A row-major [M,K].  AMODE 1: jump-concat, A[m,k] = rep[k/64][m][k%64]
// EPI 0: none.  EPI 1: +bias.  EPI 2: +bias, BN, ELU.
template<int AMODE, int EPI>
__global__ __launch_bounds__(256)
void gemm_tc(const float* __restrict__ A, const float* __restrict__ B,
             const float* __restrict__ bias,
             const float* __restrict__ gamma, const float* __restrict__ beta,
             const float* __restrict__ mean, const float* __restrict__ var,
             float* __restrict__ C, int M, int K, int NC)
{
    __shared__ __align__(16) float As[128 * 36];
    __shared__ __align__(16) float Bs[32 * 72];
    int tid = threadIdx.x;
    int warp = tid >> 5, lane = tid & 31;
    int wm = (warp >> 1) * 32;
    int wn = (warp & 1) * 32;
    int row0 = blockIdx.y * 128, col0 = blockIdx.x * 64;
    int g = lane >> 2, q = lane & 3;

    float c[2][4][4] = {};

    int ar = tid >> 3;              // A load: row 0..31
    int ac = (tid & 7) * 4;         // col 0..28 step 4
    int bk = tid >> 4;              // B load: k 0..15
    int bc = (tid & 15) * 4;        // col 0..60 step 4

    for (int k0 = 0; k0 < K; k0 += 32) {
#pragma unroll
        for (int i = 0; i < 4; i++) {
            int m = ar + i * 32;
            int gm = row0 + m;
            float4 v = make_float4(0.f, 0.f, 0.f, 0.f);
            if (gm < M) {
                if (AMODE == 0)
                    v = *(const float4*)(A + (size_t)gm * K + k0 + ac);
                else
                    v = *(const float4*)(A + (size_t)(k0 >> 6) * (NMAX * 64)
                                           + (size_t)gm * 64 + (k0 & 63) + ac);
            }
            v.x = cvt_tf32(v.x); v.y = cvt_tf32(v.y);
            v.z = cvt_tf32(v.z); v.w = cvt_tf32(v.w);
            *(float4*)(As + m * 36 + ac) = v;
        }
#pragma unroll
        for (int i = 0; i < 2; i++) {
            int kk = bk + i * 16;
            float4 v = *(const float4*)(B + (size_t)(k0 + kk) * NC + col0 + bc);
            v.x = cvt_tf32(v.x); v.y = cvt_tf32(v.y);
            v.z = cvt_tf32(v.z); v.w = cvt_tf32(v.w);
            *(float4*)(Bs + kk * 72 + bc) = v;
        }
        __syncthreads();
#pragma unroll
        for (int ks = 0; ks < 32; ks += 8) {
            unsigned a[2][4], b[4][2];
#pragma unroll
            for (int mi = 0; mi < 2; mi++) {
                const float* ap = As + (wm + mi * 16 + g) * 36 + ks + q;
                a[mi][0] = __float_as_uint(ap[0]);
                a[mi][1] = __float_as_uint(ap[8 * 36]);
                a[mi][2] = __float_as_uint(ap[4]);
                a[mi][3] = __float_as_uint(ap[8 * 36 + 4]);
            }
#pragma unroll
            for (int ni = 0; ni < 4; ni++) {
                const float* bp = Bs + (ks + q) * 72 + wn + ni * 8 + g;
                b[ni][0] = __float_as_uint(bp[0]);
                b[ni][1] = __float_as_uint(bp[4 * 72]);
            }
#pragma unroll
            for (int mi = 0; mi < 2; mi++)
#pragma unroll
                for (int ni = 0; ni < 4; ni++)
                    mma_tf32(c[mi][ni], a[mi], b[ni]);
        }
        __syncthreads();
    }

#pragma unroll
    for (int mi = 0; mi < 2; mi++)
#pragma unroll
        for (int ni = 0; ni < 4; ni++) {
            int r0 = row0 + wm + mi * 16 + g;
            int cb = col0 + wn + ni * 8 + q * 2;
#pragma unroll
            for (int h = 0; h < 2; h++) {
                int r = r0 + h * 8;
                if (r >= M) continue;
#pragma unroll
                for (int cc = 0; cc < 2; cc++) {
                    int cidx = cb + cc;
                    float v = c[mi][ni][h * 2 + cc];
                    if (EPI >= 1) v += bias[cidx];
                    if (EPI == 2) {
                        v = (v - mean[cidx]) * rsqrtf(var[cidx] + BN_EPS) * gamma[cidx] + beta[cidx];
                        v = v > 0.f ? v : expm1f(v);
                    }
                    C[(size_t)r * NC + cidx] = v;
                }
            }
        }
}

// ---------------- per-node attention coefficients ----------------
__global__ void attn_kernel(const float* __restrict__ a_src,
                            const float* __restrict__ a_dst, int n) {
    __shared__ float s_src[256], s_dst[256];
    int tid = threadIdx.x;
    for (int i = tid; i < 256; i += blockDim.x) { s_src[i] = a_src[i]; s_dst[i] = a_dst[i]; }
    __syncthreads();
    int w = blockIdx.x * (blockDim.x >> 5) + (tid >> 5);
    int lane = tid & 31;
    if (w >= n) return;
    const float* xr = g_xh + (size_t)w * 256;
    float ps[4], pd[4];
#pragma unroll
    for (int h = 0; h < 4; h++) {
        int f0 = h * 64 + lane, f1 = f0 + 32;
        float x0 = xr[f0], x1 = xr[f1];
        ps[h] = x0 * s_src[f0] + x1 * s_src[f1];
        pd[h] = x0 * s_dst[f0] + x1 * s_dst[f1];
    }
#pragma unroll
    for (int h = 0; h < 4; h++)
#pragma unroll
        for (int o = 16; o > 0; o >>= 1) {
            ps[h] += __shfl_xor_sync(0xffffffffu, ps[h], o);
            pd[h] += __shfl_xor_sync(0xffffffffu, pd[h], o);
        }
    if (lane == 0) {
#pragma unroll
        for (int h = 0; h < 4; h++) { g_as[w * 4 + h] = ps[h]; g_ad[w * 4 + h] = pd[h]; }
    }
}

// online-softmax GAT aggregation, one warp per dst node, concat output (+bias)
__global__ void agg_concat_kernel(const float* __restrict__ bias, int n) {
    int w = blockIdx.x * (blockDim.x >> 5) + (threadIdx.x >> 5);
    int lane = threadIdx.x & 31;
    if (w >= n) return;
    float m0 = -1e30f, m1 = -1e30f, m2 = -1e30f, m3 = -1e30f;
    float s0 = 0, s1 = 0, s2 = 0, s3 = 0;
    float acc[8] = {};
    float adh = (lane < 4) ? g_ad[w * 4 + lane] : 0.f;
    int e0 = g_off[w], e1 = g_off[w + 1];
    for (int e = e0; e < e1; e++) {
        int src = g_csr[e];
        float l = 0.f;
        if (lane < 4) {
            float t = g_as[src * 4 + lane] + adh;
            l = t > 0.f ? t : NEG * t;
        }
        float l0 = __shfl_sync(0xffffffffu, l, 0);
        float l1 = __shfl_sync(0xffffffffu, l, 1);
        float l2 = __shfl_sync(0xffffffffu, l, 2);
        float l3 = __shfl_sync(0xffffffffu, l, 3);
        float nm0 = fmaxf(m0, l0), nm1 = fmaxf(m1, l1), nm2 = fmaxf(m2, l2), nm3 = fmaxf(m3, l3);
        float sc0 = __expf(m0 - nm0), sc1 = __expf(m1 - nm1), sc2 = __expf(m2 - nm2), sc3 = __expf(m3 - nm3);
        float w0 = __expf(l0 - nm0), w1 = __expf(l1 - nm1), w2 = __expf(l2 - nm2), w3 = __expf(l3 - nm3);
        s0 = s0 * sc0 + w0; s1 = s1 * sc1 + w1; s2 = s2 * sc2 + w2; s3 = s3 * sc3 + w3;
        m0 = nm0; m1 = nm1; m2 = nm2; m3 = nm3;
        const float* xr = g_xh + (size_t)src * 256;
        acc[0] = acc[0] * sc0 + w0 * xr[lane];
        acc[1] = acc[1] * sc0 + w0 * xr[lane + 32];
        acc[2] = acc[2] * sc1 + w1 * xr[lane + 64];
        acc[3] = acc[3] * sc1 + w1 * xr[lane + 96];
        acc[4] = acc[4] * sc2 + w2 * xr[lane + 128];
        acc[5] = acc[5] * sc2 + w2 * xr[lane + 160];
        acc[6] = acc[6] * sc3 + w3 * xr[lane + 192];
        acc[7] = acc[7] * sc3 + w3 * xr[lane + 224];
    }
    size_t o = (size_t)w * 256;
    g_agg[o + lane]       = acc[0] / s0 + bias[lane];
    g_agg[o + lane + 32]  = acc[1] / s0 + bias[lane + 32];
    g_agg[o + lane + 64]  = acc[2] / s1 + bias[lane + 64];
    g_agg[o + lane + 96]  = acc[3] / s1 + bias[lane + 96];
    g_agg[o + lane + 128] = acc[4] / s2 + bias[lane + 128];
    g_agg[o + lane + 160] = acc[5] / s2 + bias[lane + 160];
    g_agg[o + lane + 192] = acc[6] / s3 + bias[lane + 192];
    g_agg[o + lane + 224] = acc[7] / s3 + bias[lane + 224];
}

// aggregation for layers 1/2: mean over heads + bias + BN + ELU + residual
__global__ void agg_mean_kernel(const float* __restrict__ bias,
                                const float* __restrict__ gamma, const float* __restrict__ beta,
                                const float* __restrict__ mean,  const float* __restrict__ var,
                                const float* __restrict__ h_in, float* __restrict__ h_out, int n) {
    int w = blockIdx.x * (blockDim.x >> 5) + (threadIdx.x >> 5);
    int lane = threadIdx.x & 31;
    if (w >= n) return;
    float m0 = -1e30f, m1 = -1e30f, m2 = -1e30f, m3 = -1e30f;
    float s0 = 0, s1 = 0, s2 = 0, s3 = 0;
    float acc[8] = {};
    float adh = (lane < 4) ? g_ad[w * 4 + lane] : 0.f;
    int e0 = g_off[w], e1 = g_off[w + 1];
    for (int e = e0; e < e1; e++) {
        int src = g_csr[e];
        float l = 0.f;
        if (lane < 4) {
            float t = g_as[src * 4 + lane] + adh;
            l = t > 0.f ? t : NEG * t;
        }
        float l0 = __shfl_sync(0xffffffffu, l, 0);
        float l1 = __shfl_sync(0xffffffffu, l, 1);
        float l2 = __shfl_sync(0xffffffffu, l, 2);
        float l3 = __shfl_sync(0xffffffffu, l, 3);
        float nm0 = fmaxf(m0, l0), nm1 = fmaxf(m1, l1), nm2 = fmaxf(m2, l2), nm3 = fmaxf(m3, l3);
        float sc0 = __expf(m0 - nm0), sc1 = __expf(m1 - nm1), sc2 = __expf(m2 - nm2), sc3 = __expf(m3 - nm3);
        float w0 = __expf(l0 - nm0), w1 = __expf(l1 - nm1), w2 = __expf(l2 - nm2), w3 = __expf(l3 - nm3);
        s0 = s0 * sc0 + w0; s1 = s1 * sc1 + w1; s2 = s2 * sc2 + w2; s3 = s3 * sc3 + w3;
        m0 = nm0; m1 = nm1; m2 = nm2; m3 = nm3;
        const float* xr = g_xh + (size_t)src * 256;
        acc[0] = acc[0] * sc0 + w0 * xr[lane];
        acc[1] = acc[1] * sc0 + w0 * xr[lane + 32];
        acc[2] = acc[2] * sc1 + w1 * xr[lane + 64];
        acc[3] = acc[3] * sc1 + w1 * xr[lane + 96];
        acc[4] = acc[4] * sc2 + w2 * xr[lane + 128];
        acc[5] = acc[5] * sc2 + w2 * xr[lane + 160];
        acc[6] = acc[6] * sc3 + w3 * xr[lane + 192];
        acc[7] = acc[7] * sc3 + w3 * xr[lane + 224];
    }
    float i0 = 1.f / s0, i1 = 1.f / s1, i2 = 1.f / s2, i3 = 1.f / s3;
    float v0 = 0.25f * (acc[0] * i0 + acc[2] * i1 + acc[4] * i2 + acc[6] * i3) + bias[lane];
    float v1 = 0.25f * (acc[1] * i0 + acc[3] * i1 + acc[5] * i2 + acc[7] * i3) + bias[lane + 32];
    int c0 = lane, c1 = lane + 32;
    v0 = (v0 - mean[c0]) * rsqrtf(var[c0] + BN_EPS) * gamma[c0] + beta[c0];
    v1 = (v1 - mean[c1]) * rsqrtf(var[c1] + BN_EPS) * gamma[c1] + beta[c1];
    v0 = v0 > 0.f ? v0 : expm1f(v0);
    v1 = v1 > 0.f ? v1 : expm1f(v1);
    size_t o = (size_t)w * 64;
    h_out[o + c0] = v0 + h_in[o + c0];
    h_out[o + c1] = v1 + h_in[o + c1];
}

// pooling pass 1: logits + per-graph max
__global__ void pool1_kernel(const float* __restrict__ attW, const float* __restrict__ attB,
                             const int* __restrict__ batch, int n) {
    int w = blockIdx.x * (blockDim.x >> 5) + (threadIdx.x >> 5);
    int lane = threadIdx.x & 31;
    if (w >= n) return;
    const float* hr = g_hj + (size_t)w * 64;
    float p = hr[lane] * attW[lane] + hr[lane + 32] * attW[lane + 32];
#pragma unroll
    for (int o = 16; o > 0; o >>= 1) p += __shfl_xor_sync(0xffffffffu, p, o);
    if (lane == 0) {
        float v = p + attB[0];
        g_logit[w] = v;
        atomicMax(&g_maxenc[batch[w]], fenc(v));
    }
}

// pooling pass 2: unnormalized weighted sum + denom
__global__ void pool2_kernel(const int* __restrict__ batch, int n) {
    int w = blockIdx.x * (blockDim.x >> 5) + (threadIdx.x >> 5);
    int lane = threadIdx.x & 31;
    if (w >= n) return;
    int b = batch[w];
    float ev = __expf(g_logit[w] - fdec(g_maxenc[b]));
    if (lane == 0) atomicAdd(&g_sumexp[b], ev);
    const float* hr = g_hj + (size_t)w * 64;
    atomicAdd(&g_hg[b * 64 + lane], ev * hr[lane]);
    atomicAdd(&g_hg[b * 64 + lane + 32], ev * hr[lane + 32]);
}

__global__ void classifier_kernel(const float* __restrict__ W1, const float* __restrict__ b1,
                                  const float* __restrict__ W2, const float* __restrict__ b2,
                                  float* __restrict__ out) {
    int g = threadIdx.x;
    if (g >= GRAPHS) return;
    float s = g_sumexp[g];
    float inv = (s > 0.f) ? 1.f / s : 0.f;
    float hid[32];
#pragma unroll
    for (int j = 0; j < 32; j++) {
        float a = b1[j];
        for (int c = 0; c < 64; c++) a += g_hg[g * 64 + c] * inv * W1[c * 32 + j];
        hid[j] = a > 0.f ? a : 0.f;
    }
#pragma unroll
    for (int k = 0; k < 2; k++) {
        float o = b2[k];
#pragma unroll
        for (int j = 0; j < 32; j++) o += hid[j] * W2[j * 2 + k];
        out[g * 2 + k] = o;
    }
}

// ---------------- host ----------------
extern "C" void kernel_launch(void* const* d_in, const int* in_sizes, int n_in,
                              void* d_out, int out_size) {
    const float* x        = (const float*)d_in[0];
    const int*   ei       = (const int*)d_in[1];
    const int*   batch    = (const int*)d_in[2];
    const float* conv0_W  = (const float*)d_in[3];
    const float* c0_asrc  = (const float*)d_in[4];
    const float* c0_adst  = (const float*)d_in[5];
    const float* c0_bias  = (const float*)d_in[6];
    const float* pre0_W   = (const float*)d_in[7];
    const float* pre0_b   = (const float*)d_in[8];
    const float* convs_W  = (const float*)d_in[9];
    const float* cs_asrc  = (const float*)d_in[10];
    const float* cs_adst  = (const float*)d_in[11];
    const float* cs_bias  = (const float*)d_in[12];
    const float* bn_g     = (const float*)d_in[13];
    const float* bn_b     = (const float*)d_in[14];
    const float* bn_m     = (const float*)d_in[15];
    const float* bn_v     = (const float*)d_in[16];
    const float* jump_W   = (const float*)d_in[17];
    const float* jump_b   = (const float*)d_in[18];
    const float* att_W    = (const float*)d_in[19];
    const float* att_b    = (const float*)d_in[20];
    const float* cls_W1   = (const float*)d_in[21];
    const float* cls_b1   = (const float*)d_in[22];
    const float* cls_W2   = (const float*)d_in[23];
    const float* cls_b2   = (const float*)d_in[24];

    int n = in_sizes[0] / 128;
    int e = in_sizes[1] / 2;

    float *p_xh, *p_agg, *p_rep, *p_hj;
    cudaGetSymbolAddress((void**)&p_xh,  g_xh);
    cudaGetSymbolAddress((void**)&p_agg, g_agg);
    cudaGetSymbolAddress((void**)&p_rep, g_rep);
    cudaGetSymbolAddress((void**)&p_hj,  g_hj);

    const int T = 256;
    int nb  = (n + T - 1) / T;
    int ebN = (e + T - 1) / T;
    int wb  = (n + 7) / 8;        // 8 warps per block kernels
    int mg  = (n + 127) / 128;    // GEMM row tiles

    // CSR build (self loops placed inside scan)
    init_kernel<<<nb, T>>>(n);
    count_kernel<<<ebN, T>>>(ei, e);
    scan_kernel<<<1, 1024>>>(n);
    fill_edges_kernel<<<ebN, T>>>(ei, e);

    // ---- layer 0 (concat) ----
    gemm_tc<0,0><<<dim3(4, mg), 256>>>(x, conv0_W, nullptr, nullptr, nullptr, nullptr, nullptr,
                                       p_xh, n, 128, 256);
    attn_kernel<<<wb, T>>>(c0_asrc, c0_adst, n);
    agg_concat_kernel<<<wb, T>>>(c0_bias, n);
    // pre0 projection with fused bias + BN + ELU -> rep[0]
    gemm_tc<0,2><<<dim3(1, mg), 256>>>(p_agg, pre0_W, pre0_b, bn_g, bn_b, bn_m, bn_v,
                                       p_rep, n, 256, 64);

    // ---- layers 1,2 (mean heads, fused BN/ELU/residual in agg) ----
    for (int i = 0; i < 2; i++) {
        const float* rin  = p_rep + (size_t)i * NMAX * 64;
        float*       rout = p_rep + (size_t)(i + 1) * NMAX * 64;
        gemm_tc<0,0><<<dim3(4, mg), 256>>>(rin, convs_W + (size_t)i * 64 * 256, nullptr,
                                           nullptr, nullptr, nullptr, nullptr,
                                           p_xh, n, 64, 256);
        attn_kernel<<<wb, T>>>(cs_asrc + i * 256, cs_adst + i * 256, n);
        agg_mean_kernel<<<wb, T>>>(cs_bias + i * 64,
                                   bn_g + (i + 1) * 64, bn_b + (i + 1) * 64,
                                   bn_m + (i + 1) * 64, bn_v + (i + 1) * 64,
                                   rin, rout, n);
    }

    // ---- jumping knowledge GEMM reads rep[] directly (AMODE=1), fused bias ----
    gemm_tc<1,1><<<dim3(1, mg), 256>>>(p_rep, jump_W, jump_b, nullptr, nullptr, nullptr, nullptr,
                                       p_hj, n, 192, 64);
    pool1_kernel<<<wb, T>>>(att_W, att_b, batch, n);
    pool2_kernel<<<wb, T>>>(batch, n);
    classifier_kernel<<<1, 64>>>(cls_W1, cls_b1, cls_W2, cls_b2, (float*)d_out);
}